// round 8
// baseline (speedup 1.0000x reference)
#include <cuda_runtime.h>
#include <math.h>

#define TT 20
#define MM 2000
#define NROWS (TT*MM)          // 40000, row index = t*MM + m
#define CAP 96

#define FMA2(d,a,b) asm("fma.rn.f32x2 %0,%1,%2,%0;" : "+l"(d) : "l"(a), "l"(b))
#define UNPK(lo,hi,v) asm("mov.b64 {%0,%1},%2;" : "=f"(lo), "=f"(hi) : "l"(v))

// ---------------- static scratch ----------------
__device__ float          d_maskf[NROWS];
__device__ int            d_cnt[NROWS];
__device__ float          d_dinv[NROWS];
__device__ unsigned short d_nbr[(size_t)NROWS * CAP];
__device__ float          d_bufA[(size_t)NROWS * 128];   // Z2
__device__ float          d_bufB[(size_t)NROWS * 128];   // h1 / placeholder
__device__ float          d_gpre[(size_t)NROWS * 512];   // [m*T+t][512]
__device__ float          d_lstm[(size_t)NROWS * 128];   // [m*T+t][128]

// fast nonlinearities: MUFU EX2 based, err ~1e-7 (vs 1e-3 tolerance)
__device__ __forceinline__ float sigm_f(float x) {
    return __fdividef(1.0f, 1.0f + __expf(-x));
}
__device__ __forceinline__ float tanh_f(float x) {
    return __fdividef(2.0f, 1.0f + __expf(-2.0f * x)) - 1.0f;
}

// ---------------- extraction + mask init (fused) ----------------
__global__ void k_extract(const float* __restrict__ adj, const unsigned int* __restrict__ em) {
    int t = blockIdx.y;
    int i = blockIdx.x * 256 + threadIdx.x;
    __shared__ float msm[MM];
    for (int j = threadIdx.x; j < MM; j += 256) {
        int b = j / 500, n = j % 500;
        float v = em[(b * TT + t) * 500 + n] ? 1.0f : 0.0f;
        msm[j] = v;
        if (blockIdx.x == 0) d_maskf[t * MM + j] = v;
    }
    __syncthreads();
    if (i >= MM) return;
    const float* a = adj + (size_t)t * MM * MM + i;   // column i
    unsigned short* list = d_nbr + (size_t)(t * MM + i) * CAP;
    int cnt = 0;
    #pragma unroll 8
    for (int j = 0; j < MM; j++) {
        float av = a[(size_t)j * MM];
        if (av != 0.0f && msm[j] != 0.0f) {
            if (cnt < CAP) list[cnt] = (unsigned short)j;
            cnt++;
        }
    }
    float mi = msm[i];
    d_cnt[t * MM + i] = (cnt < CAP ? cnt : CAP);
    d_dinv[t * MM + i] = (mi != 0.0f) ? rsqrtf((float)cnt + 1.0f) : 0.0f;
}

// ---------------- fused GCN1: h1 = relu( dinv_i * ((Σ dinv_j x_j) @ W1) + b1 ) ----------------
__global__ void k_agg1(const float2* __restrict__ pos2, const float* __restrict__ W1,
                       const float* __restrict__ b1, float* __restrict__ out) {
    int row = blockIdx.x;
    int f = threadIdx.x;
    int t = row / MM;
    size_t base = (size_t)t * MM;
    float di = d_dinv[row];
    float2 xi = __ldg(&pos2[row]);
    float wx0 = di * xi.x, wx1 = di * xi.y;      // self term
    int n = d_cnt[row];
    const unsigned short* lst = &d_nbr[(size_t)row * CAP];
    for (int idx = 0; idx < n; idx++) {
        size_t j = base + lst[idx];
        float dj = __ldg(&d_dinv[j]);
        float2 xj = __ldg(&pos2[j]);
        wx0 += dj * xj.x;
        wx1 += dj * xj.y;
    }
    float v = di * (wx0 * __ldg(&W1[f]) + wx1 * __ldg(&W1[128 + f])) + __ldg(&b1[f]);
    out[(size_t)row * 128 + f] = fmaxf(v, 0.0f);
}

// ---------------- GCN2 aggregation: out = (dinv_i*(Σ Z2[j] + Z2[i]) + b2) * mask ----------------
__global__ void k_agg2(const float* __restrict__ Zin, const float* __restrict__ bias,
                       float* __restrict__ out) {
    int row = blockIdx.x;
    int f = threadIdx.x;
    int t = row / MM;
    size_t base = (size_t)t * MM;
    float acc = Zin[(size_t)row * 128 + f];
    int n = d_cnt[row];
    const unsigned short* lst = &d_nbr[(size_t)row * CAP];
    for (int idx = 0; idx < n; idx++) {
        int j = lst[idx];
        acc += Zin[(base + j) * 128 + f];
    }
    float v = d_dinv[row] * acc + __ldg(&bias[f]);
    out[(size_t)row * 128 + f] = v * d_maskf[row];
}

// ---------------- tiled GEMM, K=128 fixed, packed f32x2 ----------------
// mode 0 (Z2):    A row = r,                B = W2   [k][c],  epi: *dinv[r]
// mode 1 (gates): A row = (r%20)*2000+r/20, B = W_ih [c][k],  epi: + b_ih[c]+b_hh[c]
__global__ void __launch_bounds__(256)
k_gemm(const float* __restrict__ A, const float* __restrict__ B, float* __restrict__ C,
       const float* __restrict__ bia, const float* __restrict__ bib,
       int mode, int ncols) {
    extern __shared__ float sm[];
    float* As = sm;            // [64][128]
    float* Bs = sm + 64 * 128; // [128][130]
    int r0 = blockIdx.x * 64, c0 = blockIdx.y * 128;
    int tid = threadIdx.x;

    for (int i = tid; i < 64 * 32; i += 256) {
        int row = i / 32, k4 = i % 32;
        int gr = r0 + row;
        int arow = (mode == 1) ? ((gr % TT) * MM + gr / TT) : gr;
        ((float4*)As)[row * 32 + k4] = ((const float4*)A)[(size_t)arow * 32 + k4];
    }
    if (mode == 1) {
        for (int i = tid; i < 128 * 32; i += 256) {
            int c = i / 32, k4 = i % 32;
            float4 v = ((const float4*)B)[(size_t)(c0 + c) * 32 + k4];
            Bs[c * 130 + 4 * k4 + 0] = v.x; Bs[c * 130 + 4 * k4 + 1] = v.y;
            Bs[c * 130 + 4 * k4 + 2] = v.z; Bs[c * 130 + 4 * k4 + 3] = v.w;
        }
    } else {
        for (int i = tid; i < 128 * 32; i += 256) {
            int k = i / 32, c4 = i % 32;
            float4 v = ((const float4*)B)[(size_t)k * 32 + c4];
            Bs[(4 * c4 + 0) * 130 + k] = v.x; Bs[(4 * c4 + 1) * 130 + k] = v.y;
            Bs[(4 * c4 + 2) * 130 + k] = v.z; Bs[(4 * c4 + 3) * 130 + k] = v.w;
        }
    }
    __syncthreads();

    int tx = tid % 32, ty = tid / 32;
    unsigned long long acc[8][4];
    #pragma unroll
    for (int rr = 0; rr < 8; rr++)
        #pragma unroll
        for (int cc = 0; cc < 4; cc++) acc[rr][cc] = 0ull;

    const ulonglong2* As2 = (const ulonglong2*)As;
    #pragma unroll 4
    for (int k4 = 0; k4 < 32; k4++) {
        ulonglong2 a[8];
        #pragma unroll
        for (int rr = 0; rr < 8; rr++) a[rr] = As2[(ty * 8 + rr) * 32 + k4];
        #pragma unroll
        for (int cc = 0; cc < 4; cc++) {
            int c = tx + 32 * cc;
            const unsigned long long* bp = (const unsigned long long*)(Bs + c * 130 + 4 * k4);
            unsigned long long b0 = bp[0], b1 = bp[1];
            #pragma unroll
            for (int rr = 0; rr < 8; rr++) {
                FMA2(acc[rr][cc], a[rr].x, b0);
                FMA2(acc[rr][cc], a[rr].y, b1);
            }
        }
    }
    #pragma unroll
    for (int cc = 0; cc < 4; cc++) {
        int c = tx + 32 * cc;
        float bv = (mode == 1) ? (__ldg(&bia[c0 + c]) + __ldg(&bib[c0 + c])) : 0.0f;
        #pragma unroll
        for (int rr = 0; rr < 8; rr++) {
            int r = r0 + ty * 8 + rr;
            float lo, hi; UNPK(lo, hi, acc[rr][cc]);
            float v = lo + hi;
            if (mode == 1) v += bv;
            else           v *= d_dinv[r];
            C[(size_t)r * ncols + c0 + c] = v;
        }
    }
}

// ---------------- persistent LSTM: 20 blocks, 256 threads, 2 gate-rows/thread ----------------
// Thread g -> (q = g&3 gate type, j = g>>2 in [0,64)): owns gate rows q*128+j and
// q*128+j+64. Weights: 48 ull/gate in registers (192 regs), 16 floats/gate tail in
// smem. h broadcast from smem (8 warps -> 256 wf vs 512 at 16 warps). Shuffle gate
// exchange, double-buffered h, one barrier/step.
__global__ void __launch_bounds__(256, 1)
k_lstm(const float* __restrict__ Whh) {
    extern __shared__ float sm[];
    float* Wq  = sm;                 // [16][256] float4: k=96..127 tails, gateA rows 0..7, gateB rows 8..15
    float* hsm = sm + 16 * 256 * 4;  // [2][128] double-buffered h
    int t = blockIdx.x, g = threadIdx.x;
    int q = g & 3, j = g >> 2;       // j in [0,64)
    int rowA = q * 128 + j;
    int rowB = rowA + 64;

    unsigned long long wA[48], wB[48];
    const unsigned long long* wra = (const unsigned long long*)(Whh + (size_t)rowA * 128);
    const unsigned long long* wrb = (const unsigned long long*)(Whh + (size_t)rowB * 128);
    #pragma unroll
    for (int i = 0; i < 48; i++) { wA[i] = wra[i]; wB[i] = wrb[i]; }
    #pragma unroll
    for (int kq = 0; kq < 8; kq++) {
        ((float4*)Wq)[kq * 256 + g]       = __ldg((const float4*)(Whh + (size_t)rowA * 128 + 96 + 4 * kq));
        ((float4*)Wq)[(8 + kq) * 256 + g] = __ldg((const float4*)(Whh + (size_t)rowB * 128 + 96 + 4 * kq));
    }

    float cA = 0.0f, cB = 0.0f;
    if (g < 128) hsm[g] = 0.0f;      // buffer 0
    __syncthreads();

    float ngA = d_gpre[(size_t)t * 512 + rowA];   // m = 0 prefetch
    float ngB = d_gpre[(size_t)t * 512 + rowB];
    const ulonglong2* wq2 = (const ulonglong2*)Wq;
    for (int m = 0; m < MM; m++) {
        float gpA = ngA, gpB = ngB;
        if (m < MM - 1) {
            size_t nb = (size_t)((m + 1) * TT + t) * 512;
            ngA = d_gpre[nb + rowA];
            ngB = d_gpre[nb + rowB];
        }
        const ulonglong2* h2 = (const ulonglong2*)(hsm + (m & 1) * 128);
        unsigned long long aA0 = 0ull, aA1 = 0ull, aB0 = 0ull, aB1 = 0ull;
        #pragma unroll
        for (int jj = 0; jj < 24; jj++) {         // k = 0..95: register weights
            ulonglong2 hv = h2[jj];
            FMA2(aA0, hv.x, wA[2 * jj]);
            FMA2(aA1, hv.y, wA[2 * jj + 1]);
            FMA2(aB0, hv.x, wB[2 * jj]);
            FMA2(aB1, hv.y, wB[2 * jj + 1]);
        }
        #pragma unroll
        for (int kq = 0; kq < 8; kq++) {          // k = 96..127: smem weight tails
            ulonglong2 hv = h2[24 + kq];
            ulonglong2 wa = wq2[kq * 256 + g];
            ulonglong2 wb = wq2[(8 + kq) * 256 + g];
            FMA2(aA0, hv.x, wa.x);
            FMA2(aA1, hv.y, wa.y);
            FMA2(aB0, hv.x, wb.x);
            FMA2(aB1, hv.y, wb.y);
        }
        float lo, hi;
        UNPK(lo, hi, aA0); float pA = lo + hi;
        UNPK(lo, hi, aA1); pA += lo + hi; pA += gpA;
        UNPK(lo, hi, aB0); float pB = lo + hi;
        UNPK(lo, hi, aB1); pB += lo + hi; pB += gpB;
        // branchless nonlinearity: tanh(x) = 2*sigm(2x)-1
        float xA = (q == 2) ? 2.0f * pA : pA;
        float xB = (q == 2) ? 2.0f * pB : pB;
        float sA = sigm_f(xA), sB = sigm_f(xB);
        float actA = (q == 2) ? fmaf(2.0f, sA, -1.0f) : sA;
        float actB = (q == 2) ? fmaf(2.0f, sB, -1.0f) : sB;
        // gate exchange within warp: lane q=0 gathers f,g,o from lanes +1,+2,+3
        float a1A = __shfl_down_sync(0xffffffffu, actA, 1);
        float a2A = __shfl_down_sync(0xffffffffu, actA, 2);
        float a3A = __shfl_down_sync(0xffffffffu, actA, 3);
        float a1B = __shfl_down_sync(0xffffffffu, actB, 1);
        float a2B = __shfl_down_sync(0xffffffffu, actB, 2);
        float a3B = __shfl_down_sync(0xffffffffu, actB, 3);
        if (q == 0) {
            cA = a1A * cA + actA * a2A;           // f*c + i*g
            cB = a1B * cB + actB * a2B;
            float hA = a3A * tanh_f(cA);          // o*tanh(c)
            float hB = a3B * tanh_f(cB);
            int wb = ((m & 1) ^ 1) * 128;
            hsm[wb + j] = hA;
            hsm[wb + 64 + j] = hB;
            float* dst = &d_lstm[(size_t)(m * TT + t) * 128];
            dst[j] = hA;
            dst[64 + j] = hB;
        }
        __syncthreads();
    }
}

// ---------------- fused FC1(relu)+FC2, 64 rows/block, packed f32x2 ----------------
__global__ void __launch_bounds__(256)
k_fc(const float* __restrict__ fc1w, const float* __restrict__ fc1b,
     const float* __restrict__ fc2w, const float* __restrict__ fc2b,
     float* __restrict__ out) {
    extern __shared__ float sm[];
    float* w1t = sm;                   // [64][130]
    float* w2t = w1t + 64 * 130;       // [32][66]
    float* xs  = w2t + 32 * 66;        // [64][128]
    float* mid = xs  + 64 * 128;       // [64][66]
    int tid = threadIdx.x;

    for (int i = tid; i < 128 * 64; i += 256) {
        int k = i >> 6, cc = i & 63;
        w1t[cc * 130 + k] = fc1w[i];
    }
    for (int i = tid; i < 64 * 32; i += 256) {
        int k = i >> 5, o = i & 31;
        w2t[o * 66 + k] = fc2w[i];
    }
    int rbase = blockIdx.x * 64;
    for (int i = tid; i < 64 * 32; i += 256)
        ((float4*)xs)[i] = ((const float4*)d_lstm)[(size_t)rbase * 32 + i];
    __syncthreads();

    int r = tid >> 2, q = tid & 3;
    {
        unsigned long long acc[16];
        #pragma unroll
        for (int j = 0; j < 16; j++) acc[j] = 0ull;
        const unsigned long long* xr = (const unsigned long long*)(xs + r * 128);
        #pragma unroll 4
        for (int kp = 0; kp < 64; kp++) {
            unsigned long long xv = xr[kp];
            #pragma unroll
            for (int j = 0; j < 16; j++)
                FMA2(acc[j], xv, *(const unsigned long long*)(w1t + (q * 16 + j) * 130 + 2 * kp));
        }
        #pragma unroll
        for (int j = 0; j < 16; j++) {
            float lo, hi; UNPK(lo, hi, acc[j]);
            int cc = q * 16 + j;
            mid[r * 66 + cc] = fmaxf(lo + hi + __ldg(&fc1b[cc]), 0.0f);
        }
    }
    __syncthreads();
    {
        unsigned long long acc[8];
        #pragma unroll
        for (int j = 0; j < 8; j++) acc[j] = 0ull;
        const unsigned long long* mr = (const unsigned long long*)(mid + r * 66);
        #pragma unroll 4
        for (int kp = 0; kp < 32; kp++) {
            unsigned long long mv = mr[kp];
            #pragma unroll
            for (int j = 0; j < 8; j++)
                FMA2(acc[j], mv, *(const unsigned long long*)(w2t + (q * 8 + j) * 66 + 2 * kp));
        }
        #pragma unroll
        for (int j = 0; j < 8; j++) {
            float lo, hi; UNPK(lo, hi, acc[j]);
            int o = q * 8 + j;
            out[(size_t)(rbase + r) * 32 + o] = lo + hi + __ldg(&fc2b[o]);
        }
    }
}

// ---------------- launch ----------------
extern "C" void kernel_launch(void* const* d_in, const int* in_sizes, int n_in,
                              void* d_out, int out_size) {
    const float* positions = (const float*)d_in[0];
    const float* adjacency = (const float*)d_in[1];
    const unsigned int* ego = (const unsigned int*)d_in[2];
    const float* W1   = (const float*)d_in[3];
    const float* b1   = (const float*)d_in[4];
    const float* W2   = (const float*)d_in[5];
    const float* b2   = (const float*)d_in[6];
    const float* W_ih = (const float*)d_in[7];
    const float* W_hh = (const float*)d_in[8];
    const float* b_ih = (const float*)d_in[9];
    const float* b_hh = (const float*)d_in[10];
    const float* fc1w = (const float*)d_in[11];
    const float* fc1b = (const float*)d_in[12];
    const float* fc2w = (const float*)d_in[13];
    const float* fc2b = (const float*)d_in[14];
    float* out = (float*)d_out;

    static const int GEMM_SMEM = (64 * 128 + 128 * 130) * 4;            // 99328
    static const int LSTM_SMEM = (16 * 256 * 4 + 256) * 4;              // 66560
    static const int FC_SMEM   = (64 * 130 + 32 * 66 + 64 * 128 + 64 * 66) * 4;  // 91392
    cudaFuncSetAttribute(k_gemm, cudaFuncAttributeMaxDynamicSharedMemorySize, GEMM_SMEM);
    cudaFuncSetAttribute(k_lstm, cudaFuncAttributeMaxDynamicSharedMemorySize, LSTM_SMEM);
    cudaFuncSetAttribute(k_fc,   cudaFuncAttributeMaxDynamicSharedMemorySize, FC_SMEM);

    float* bufA; cudaGetSymbolAddress((void**)&bufA, d_bufA);
    float* bufB; cudaGetSymbolAddress((void**)&bufB, d_bufB);
    float* gpre; cudaGetSymbolAddress((void**)&gpre, d_gpre);

    // launch index:                                                       idx
    k_extract<<<dim3(8, TT), 256>>>(adjacency, ego);                    // 0
    k_agg1<<<NROWS, 128>>>((const float2*)positions, W1, b1, bufB);     // 1  h1
    k_gemm<<<dim3(625, 1), 256, GEMM_SMEM>>>(bufB, W2, bufA, 0, 0, 0, 128);      // 2  Z2
    k_agg2<<<NROWS, 128>>>(bufA, b2, bufB);                             // 3  placeholder
    k_gemm<<<dim3(625, 4), 256, GEMM_SMEM>>>(bufB, W_ih, gpre, b_ih, b_hh, 1, 512); // 4
    k_lstm<<<TT, 256, LSTM_SMEM>>>(W_hh);                               // 5
    k_fc<<<625, 256, FC_SMEM>>>(fc1w, fc1b, fc2w, fc2b, out);           // 6
}

// round 9
// speedup vs baseline: 1.1258x; 1.1258x over previous
#include <cuda_runtime.h>
#include <math.h>

#define TT 20
#define MM 2000
#define NROWS (TT*MM)          // 40000, row index = t*MM + m
#define NCHUNK 4
#define JCH (MM/NCHUNK)        // 500
#define SEG 24                 // per-chunk neighbor capacity
#define CAP (NCHUNK*SEG)       // 96

#define FMA2(d,a,b) asm("fma.rn.f32x2 %0,%1,%2,%0;" : "+l"(d) : "l"(a), "l"(b))
#define UNPK(lo,hi,v) asm("mov.b64 {%0,%1},%2;" : "=f"(lo), "=f"(hi) : "l"(v))

// ---------------- static scratch ----------------
__device__ float          d_maskf[NROWS];
__device__ int            d_cnt4[NCHUNK*NROWS];
__device__ float          d_dinv[NROWS];
__device__ unsigned short d_nbr[(size_t)NROWS * CAP];
__device__ float          d_bufA[(size_t)NROWS * 128];   // Z2
__device__ float          d_bufB[(size_t)NROWS * 128];   // h1 / placeholder
__device__ float          d_gpre[(size_t)NROWS * 512];   // [m*T+t][512]
__device__ float          d_lstm[(size_t)NROWS * 128];   // [m*T+t][128]

// fast nonlinearities: MUFU EX2 based, err ~1e-7 (vs 1e-3 tolerance)
__device__ __forceinline__ float sigm_f(float x) {
    return __fdividef(1.0f, 1.0f + __expf(-x));
}
__device__ __forceinline__ float tanh_f(float x) {
    return __fdividef(2.0f, 1.0f + __expf(-2.0f * x)) - 1.0f;
}

// ---------------- chunked extraction: 640 CTAs, each scans a 500-row j-chunk ----------------
__global__ void k_extract(const float* __restrict__ adj, const unsigned int* __restrict__ em) {
    int t = blockIdx.y;
    int ch = blockIdx.z;
    int j0 = ch * JCH;
    int i = blockIdx.x * 256 + threadIdx.x;
    __shared__ float msm[JCH];
    for (int j = threadIdx.x; j < JCH; j += 256) {
        int gj = j0 + j;
        int b = gj / 500, n = gj % 500;           // JCH==500 so b==ch, n==j; keep general
        msm[j] = em[(b * TT + t) * 500 + n] ? 1.0f : 0.0f;
    }
    __syncthreads();
    if (i >= MM) return;
    const float* a = adj + (size_t)t * MM * MM + (size_t)j0 * MM + i;   // column i, chunk rows
    unsigned short* list = d_nbr + (size_t)(t * MM + i) * CAP + ch * SEG;
    int cnt = 0;
    #pragma unroll 8
    for (int j = 0; j < JCH; j++) {
        float av = a[(size_t)j * MM];
        if (av != 0.0f && msm[j] != 0.0f) {
            if (cnt < SEG) list[cnt] = (unsigned short)(j0 + j);
            cnt++;
        }
    }
    d_cnt4[ch * NROWS + t * MM + i] = (cnt < SEG ? cnt : SEG);
}

// ---------------- degrees, mask, dinv ----------------
__global__ void k_dinv(const unsigned int* __restrict__ em) {
    int idx = blockIdx.x * 256 + threadIdx.x;
    if (idx >= NROWS) return;
    int t = idx / MM, i = idx % MM;
    int b = i / 500, n = i % 500;
    float mi = em[(b * TT + t) * 500 + n] ? 1.0f : 0.0f;
    int cnt = d_cnt4[idx] + d_cnt4[NROWS + idx] + d_cnt4[2 * NROWS + idx] + d_cnt4[3 * NROWS + idx];
    d_maskf[idx] = mi;
    d_dinv[idx] = (mi != 0.0f) ? rsqrtf((float)cnt + 1.0f) : 0.0f;
}

// ---------------- fused GCN1: h1 = relu( dinv_i * ((Σ dinv_j x_j) @ W1) + b1 ) ----------------
__global__ void k_agg1(const float2* __restrict__ pos2, const float* __restrict__ W1,
                       const float* __restrict__ b1, float* __restrict__ out) {
    int row = blockIdx.x;
    int f = threadIdx.x;
    int t = row / MM;
    size_t base = (size_t)t * MM;
    float di = d_dinv[row];
    float2 xi = __ldg(&pos2[row]);
    float wx0 = di * xi.x, wx1 = di * xi.y;      // self term
    const unsigned short* lrow = &d_nbr[(size_t)row * CAP];
    #pragma unroll
    for (int ch = 0; ch < NCHUNK; ch++) {
        int n = d_cnt4[ch * NROWS + row];
        const unsigned short* lst = lrow + ch * SEG;
        for (int idx = 0; idx < n; idx++) {
            size_t j = base + lst[idx];
            float dj = __ldg(&d_dinv[j]);
            float2 xj = __ldg(&pos2[j]);
            wx0 += dj * xj.x;
            wx1 += dj * xj.y;
        }
    }
    float v = di * (wx0 * __ldg(&W1[f]) + wx1 * __ldg(&W1[128 + f])) + __ldg(&b1[f]);
    out[(size_t)row * 128 + f] = fmaxf(v, 0.0f);
}

// ---------------- GCN2 aggregation: out = (dinv_i*(Σ Z2[j] + Z2[i]) + b2) * mask ----------------
__global__ void k_agg2(const float* __restrict__ Zin, const float* __restrict__ bias,
                       float* __restrict__ out) {
    int row = blockIdx.x;
    int f = threadIdx.x;
    int t = row / MM;
    size_t base = (size_t)t * MM;
    float acc = Zin[(size_t)row * 128 + f];
    const unsigned short* lrow = &d_nbr[(size_t)row * CAP];
    #pragma unroll
    for (int ch = 0; ch < NCHUNK; ch++) {
        int n = d_cnt4[ch * NROWS + row];
        const unsigned short* lst = lrow + ch * SEG;
        for (int idx = 0; idx < n; idx++) {
            int j = lst[idx];
            acc += Zin[(base + j) * 128 + f];
        }
    }
    float v = d_dinv[row] * acc + __ldg(&bias[f]);
    out[(size_t)row * 128 + f] = v * d_maskf[row];
}

// ---------------- tiled GEMM, K=128 fixed, packed f32x2 ----------------
// mode 0 (Z2):    A row = r,                B = W2   [k][c],  epi: *dinv[r]
// mode 1 (gates): A row = (r%20)*2000+r/20, B = W_ih [c][k],  epi: + b_ih[c]+b_hh[c]
__global__ void __launch_bounds__(256)
k_gemm(const float* __restrict__ A, const float* __restrict__ B, float* __restrict__ C,
       const float* __restrict__ bia, const float* __restrict__ bib,
       int mode, int ncols) {
    extern __shared__ float sm[];
    float* As = sm;            // [64][128]
    float* Bs = sm + 64 * 128; // [128][130]
    int r0 = blockIdx.x * 64, c0 = blockIdx.y * 128;
    int tid = threadIdx.x;

    for (int i = tid; i < 64 * 32; i += 256) {
        int row = i / 32, k4 = i % 32;
        int gr = r0 + row;
        int arow = (mode == 1) ? ((gr % TT) * MM + gr / TT) : gr;
        ((float4*)As)[row * 32 + k4] = ((const float4*)A)[(size_t)arow * 32 + k4];
    }
    if (mode == 1) {
        for (int i = tid; i < 128 * 32; i += 256) {
            int c = i / 32, k4 = i % 32;
            float4 v = ((const float4*)B)[(size_t)(c0 + c) * 32 + k4];
            Bs[c * 130 + 4 * k4 + 0] = v.x; Bs[c * 130 + 4 * k4 + 1] = v.y;
            Bs[c * 130 + 4 * k4 + 2] = v.z; Bs[c * 130 + 4 * k4 + 3] = v.w;
        }
    } else {
        for (int i = tid; i < 128 * 32; i += 256) {
            int k = i / 32, c4 = i % 32;
            float4 v = ((const float4*)B)[(size_t)k * 32 + c4];
            Bs[(4 * c4 + 0) * 130 + k] = v.x; Bs[(4 * c4 + 1) * 130 + k] = v.y;
            Bs[(4 * c4 + 2) * 130 + k] = v.z; Bs[(4 * c4 + 3) * 130 + k] = v.w;
        }
    }
    __syncthreads();

    int tx = tid % 32, ty = tid / 32;
    unsigned long long acc[8][4];
    #pragma unroll
    for (int rr = 0; rr < 8; rr++)
        #pragma unroll
        for (int cc = 0; cc < 4; cc++) acc[rr][cc] = 0ull;

    const ulonglong2* As2 = (const ulonglong2*)As;
    #pragma unroll 4
    for (int k4 = 0; k4 < 32; k4++) {
        ulonglong2 a[8];
        #pragma unroll
        for (int rr = 0; rr < 8; rr++) a[rr] = As2[(ty * 8 + rr) * 32 + k4];
        #pragma unroll
        for (int cc = 0; cc < 4; cc++) {
            int c = tx + 32 * cc;
            const unsigned long long* bp = (const unsigned long long*)(Bs + c * 130 + 4 * k4);
            unsigned long long b0 = bp[0], b1 = bp[1];
            #pragma unroll
            for (int rr = 0; rr < 8; rr++) {
                FMA2(acc[rr][cc], a[rr].x, b0);
                FMA2(acc[rr][cc], a[rr].y, b1);
            }
        }
    }
    #pragma unroll
    for (int cc = 0; cc < 4; cc++) {
        int c = tx + 32 * cc;
        float bv = (mode == 1) ? (__ldg(&bia[c0 + c]) + __ldg(&bib[c0 + c])) : 0.0f;
        #pragma unroll
        for (int rr = 0; rr < 8; rr++) {
            int r = r0 + ty * 8 + rr;
            float lo, hi; UNPK(lo, hi, acc[rr][cc]);
            float v = lo + hi;
            if (mode == 1) v += bv;
            else           v *= d_dinv[r];
            C[(size_t)r * ncols + c0 + c] = v;
        }
    }
}

// ---------------- persistent LSTM: 20 blocks, 512 threads (R7 config) ----------------
// Thread g -> (unit j = g>>2, gate q = g&3): gate exchange via 3x shfl_down.
// h double-buffered in smem -> ONE __syncthreads per step. Weight row = q*128+j:
// [0:96) in 48 ull registers, [96:128) in smem. Branchless single-MUFU nonlinearity.
__global__ void __launch_bounds__(512, 1)
k_lstm(const float* __restrict__ Whh) {
    extern __shared__ float sm[];
    float* Wq  = sm;                 // [8][512] float4 : W_hh[row][96+4kq .. +3]
    float* hsm = sm + 8 * 512 * 4;   // [2][128] double-buffered h
    int t = blockIdx.x, g = threadIdx.x;
    int q = g & 3, j = g >> 2;
    int grow = q * 128 + j;          // gate row in [512]

    unsigned long long w[48];
    const unsigned long long* wrow = (const unsigned long long*)(Whh + (size_t)grow * 128);
    #pragma unroll
    for (int i = 0; i < 48; i++) w[i] = wrow[i];
    #pragma unroll
    for (int kq = 0; kq < 8; kq++)
        ((float4*)Wq)[kq * 512 + g] = __ldg((const float4*)(Whh + (size_t)grow * 128 + 96 + 4 * kq));

    float c = 0.0f;
    if (g < 128) hsm[g] = 0.0f;      // buffer 0
    __syncthreads();

    float nextg = d_gpre[(size_t)t * 512 + grow];   // m = 0
    const ulonglong2* wq2 = (const ulonglong2*)Wq;
    for (int m = 0; m < MM; m++) {
        float gp = nextg;
        if (m < MM - 1) nextg = d_gpre[(size_t)((m + 1) * TT + t) * 512 + grow];
        const ulonglong2* h2 = (const ulonglong2*)(hsm + (m & 1) * 128);
        unsigned long long accA = 0ull, accB = 0ull;
        #pragma unroll
        for (int jj = 0; jj < 24; jj++) {         // k = 0..95, register weights
            ulonglong2 hv = h2[jj];
            FMA2(accA, hv.x, w[2 * jj]);
            FMA2(accB, hv.y, w[2 * jj + 1]);
        }
        #pragma unroll
        for (int kq = 0; kq < 8; kq++) {          // k = 96..127, smem weights
            ulonglong2 hv = h2[24 + kq];
            ulonglong2 wv = wq2[kq * 512 + g];
            FMA2(accA, hv.x, wv.x);
            FMA2(accB, hv.y, wv.y);
        }
        float loA, hiA, loB, hiB;
        UNPK(loA, hiA, accA); UNPK(loB, hiB, accB);
        float part = (loA + hiA) + (loB + hiB) + gp;
        // branchless nonlinearity: tanh(x) = 2*sigm(2x)-1
        float xin = (q == 2) ? 2.0f * part : part;
        float s = sigm_f(xin);
        float act = (q == 2) ? fmaf(2.0f, s, -1.0f) : s;
        // gate exchange within warp: lanes q=0 gather f,g,o from lanes +1,+2,+3
        float a1 = __shfl_down_sync(0xffffffffu, act, 1);
        float a2 = __shfl_down_sync(0xffffffffu, act, 2);
        float a3 = __shfl_down_sync(0xffffffffu, act, 3);
        if (q == 0) {
            c = a1 * c + act * a2;                // f*c + i*g
            float hn = a3 * tanh_f(c);            // o*tanh(c)
            hsm[((m & 1) ^ 1) * 128 + j] = hn;    // write buffer
            d_lstm[(size_t)(m * TT + t) * 128 + j] = hn;
        }
        __syncthreads();
    }
}

// ---------------- fused FC1(relu)+FC2, 64 rows/block, packed f32x2 ----------------
__global__ void __launch_bounds__(256)
k_fc(const float* __restrict__ fc1w, const float* __restrict__ fc1b,
     const float* __restrict__ fc2w, const float* __restrict__ fc2b,
     float* __restrict__ out) {
    extern __shared__ float sm[];
    float* w1t = sm;                   // [64][130]
    float* w2t = w1t + 64 * 130;       // [32][66]
    float* xs  = w2t + 32 * 66;        // [64][128]
    float* mid = xs  + 64 * 128;       // [64][66]
    int tid = threadIdx.x;

    for (int i = tid; i < 128 * 64; i += 256) {
        int k = i >> 6, cc = i & 63;
        w1t[cc * 130 + k] = fc1w[i];
    }
    for (int i = tid; i < 64 * 32; i += 256) {
        int k = i >> 5, o = i & 31;
        w2t[o * 66 + k] = fc2w[i];
    }
    int rbase = blockIdx.x * 64;
    for (int i = tid; i < 64 * 32; i += 256)
        ((float4*)xs)[i] = ((const float4*)d_lstm)[(size_t)rbase * 32 + i];
    __syncthreads();

    int r = tid >> 2, q = tid & 3;
    {
        unsigned long long acc[16];
        #pragma unroll
        for (int j = 0; j < 16; j++) acc[j] = 0ull;
        const unsigned long long* xr = (const unsigned long long*)(xs + r * 128);
        #pragma unroll 4
        for (int kp = 0; kp < 64; kp++) {
            unsigned long long xv = xr[kp];
            #pragma unroll
            for (int j = 0; j < 16; j++)
                FMA2(acc[j], xv, *(const unsigned long long*)(w1t + (q * 16 + j) * 130 + 2 * kp));
        }
        #pragma unroll
        for (int j = 0; j < 16; j++) {
            float lo, hi; UNPK(lo, hi, acc[j]);
            int cc = q * 16 + j;
            mid[r * 66 + cc] = fmaxf(lo + hi + __ldg(&fc1b[cc]), 0.0f);
        }
    }
    __syncthreads();
    {
        unsigned long long acc[8];
        #pragma unroll
        for (int j = 0; j < 8; j++) acc[j] = 0ull;
        const unsigned long long* mr = (const unsigned long long*)(mid + r * 66);
        #pragma unroll 4
        for (int kp = 0; kp < 32; kp++) {
            unsigned long long mv = mr[kp];
            #pragma unroll
            for (int j = 0; j < 8; j++)
                FMA2(acc[j], mv, *(const unsigned long long*)(w2t + (q * 8 + j) * 66 + 2 * kp));
        }
        #pragma unroll
        for (int j = 0; j < 8; j++) {
            float lo, hi; UNPK(lo, hi, acc[j]);
            int o = q * 8 + j;
            out[(size_t)(rbase + r) * 32 + o] = lo + hi + __ldg(&fc2b[o]);
        }
    }
}

// ---------------- launch ----------------
extern "C" void kernel_launch(void* const* d_in, const int* in_sizes, int n_in,
                              void* d_out, int out_size) {
    const float* positions = (const float*)d_in[0];
    const float* adjacency = (const float*)d_in[1];
    const unsigned int* ego = (const unsigned int*)d_in[2];
    const float* W1   = (const float*)d_in[3];
    const float* b1   = (const float*)d_in[4];
    const float* W2   = (const float*)d_in[5];
    const float* b2   = (const float*)d_in[6];
    const float* W_ih = (const float*)d_in[7];
    const float* W_hh = (const float*)d_in[8];
    const float* b_ih = (const float*)d_in[9];
    const float* b_hh = (const float*)d_in[10];
    const float* fc1w = (const float*)d_in[11];
    const float* fc1b = (const float*)d_in[12];
    const float* fc2w = (const float*)d_in[13];
    const float* fc2b = (const float*)d_in[14];
    float* out = (float*)d_out;

    static const int GEMM_SMEM = (64 * 128 + 128 * 130) * 4;            // 99328
    static const int LSTM_SMEM = (8 * 512 * 4 + 256) * 4;               // 66560
    static const int FC_SMEM   = (64 * 130 + 32 * 66 + 64 * 128 + 64 * 66) * 4;  // 91392
    cudaFuncSetAttribute(k_gemm, cudaFuncAttributeMaxDynamicSharedMemorySize, GEMM_SMEM);
    cudaFuncSetAttribute(k_lstm, cudaFuncAttributeMaxDynamicSharedMemorySize, LSTM_SMEM);
    cudaFuncSetAttribute(k_fc,   cudaFuncAttributeMaxDynamicSharedMemorySize, FC_SMEM);

    float* bufA; cudaGetSymbolAddress((void**)&bufA, d_bufA);
    float* bufB; cudaGetSymbolAddress((void**)&bufB, d_bufB);
    float* gpre; cudaGetSymbolAddress((void**)&gpre, d_gpre);

    k_extract<<<dim3(8, TT, NCHUNK), 256>>>(adjacency, ego);
    k_dinv<<<(NROWS + 255) / 256, 256>>>(ego);
    k_agg1<<<NROWS, 128>>>((const float2*)positions, W1, b1, bufB);     // h1
    k_gemm<<<dim3(625, 1), 256, GEMM_SMEM>>>(bufB, W2, bufA, 0, 0, 0, 128);      // Z2
    k_agg2<<<NROWS, 128>>>(bufA, b2, bufB);                             // placeholder
    k_gemm<<<dim3(625, 4), 256, GEMM_SMEM>>>(bufB, W_ih, gpre, b_ih, b_hh, 1, 512);
    k_lstm<<<TT, 512, LSTM_SMEM>>>(W_hh);
    k_fc<<<625, 256, FC_SMEM>>>(fc1w, fc1b, fc2w, fc2b, out);
}

// round 10
// speedup vs baseline: 1.2384x; 1.1000x over previous
#include <cuda_runtime.h>
#include <cuda_bf16.h>
#include <math.h>

#define TT 20
#define MM 2000
#define NROWS (TT*MM)          // 40000, row index = t*MM + m
#define NCHUNK 4
#define JCH (MM/NCHUNK)        // 500
#define SEG 24                 // per-chunk neighbor capacity
#define CAP (NCHUNK*SEG)       // 96

#define FMA2(d,a,b) asm("fma.rn.f32x2 %0,%1,%2,%0;" : "+l"(d) : "l"(a), "l"(b))
#define UNPK(lo,hi,v) asm("mov.b64 {%0,%1},%2;" : "=f"(lo), "=f"(hi) : "l"(v))

// ---------------- static scratch ----------------
__device__ float          d_maskf[NROWS];
__device__ int            d_cnt4[NCHUNK*NROWS];
__device__ int            d_deg[NROWS];      // zero-init; self-resetting
__device__ int            d_tick[NROWS];     // zero-init; self-resetting
__device__ float          d_dinv[NROWS];
__device__ unsigned short d_nbr[(size_t)NROWS * CAP];
__device__ float          d_bufA[(size_t)NROWS * 128];   // Z2
__device__ float          d_bufB[(size_t)NROWS * 128];   // h1 / placeholder
__device__ float          d_gpre[(size_t)NROWS * 512];   // [m*T+t][512]
__device__ float          d_lstm[(size_t)NROWS * 128];   // [m*T+t][128]

// fast nonlinearities: MUFU EX2 based, err ~1e-7 (vs 1e-3 tolerance)
__device__ __forceinline__ float sigm_f(float x) {
    return __fdividef(1.0f, 1.0f + __expf(-x));
}
__device__ __forceinline__ float tanh_f(float x) {
    return __fdividef(2.0f, 1.0f + __expf(-2.0f * x)) - 1.0f;
}

// ---------------- chunked extraction + fused degree/dinv (atomic ticket) ----------------
__global__ void k_extract(const float* __restrict__ adj, const unsigned int* __restrict__ em) {
    int t = blockIdx.y;
    int ch = blockIdx.z;
    int j0 = ch * JCH;
    int i = blockIdx.x * 256 + threadIdx.x;
    __shared__ float msm[JCH];
    for (int j = threadIdx.x; j < JCH; j += 256) {
        int gj = j0 + j;
        int b = gj / 500, n = gj % 500;
        msm[j] = em[(b * TT + t) * 500 + n] ? 1.0f : 0.0f;
    }
    __syncthreads();
    if (i >= MM) return;
    const float* a = adj + (size_t)t * MM * MM + (size_t)j0 * MM + i;   // column i, chunk rows
    int idx = t * MM + i;
    unsigned short* list = d_nbr + (size_t)idx * CAP + ch * SEG;
    int cnt = 0;
    #pragma unroll 8
    for (int j = 0; j < JCH; j++) {
        float av = a[(size_t)j * MM];
        if (av != 0.0f && msm[j] != 0.0f) {
            if (cnt < SEG) list[cnt] = (unsigned short)(j0 + j);
            cnt++;
        }
    }
    int cc = (cnt < SEG ? cnt : SEG);
    d_cnt4[ch * NROWS + idx] = cc;
    atomicAdd(&d_deg[idx], cc);
    __threadfence();
    int done = atomicAdd(&d_tick[idx], 1);
    if (done == NCHUNK - 1) {            // last chunk for this column: finalize
        int tot = atomicAdd(&d_deg[idx], 0);
        int b = i / 500, n = i % 500;
        float mi = em[(b * TT + t) * 500 + n] ? 1.0f : 0.0f;
        d_maskf[idx] = mi;
        d_dinv[idx] = (mi != 0.0f) ? rsqrtf((float)tot + 1.0f) : 0.0f;
        d_deg[idx] = 0;                  // self-reset for next graph replay
        d_tick[idx] = 0;
    }
}

// ---------------- fused GCN1: h1 = relu( dinv_i * ((Σ dinv_j x_j) @ W1) + b1 ) ----------------
__global__ void k_agg1(const float2* __restrict__ pos2, const float* __restrict__ W1,
                       const float* __restrict__ b1, float* __restrict__ out) {
    int row = blockIdx.x;
    int f = threadIdx.x;
    int t = row / MM;
    size_t base = (size_t)t * MM;
    float di = d_dinv[row];
    float2 xi = __ldg(&pos2[row]);
    float wx0 = di * xi.x, wx1 = di * xi.y;      // self term
    const unsigned short* lrow = &d_nbr[(size_t)row * CAP];
    #pragma unroll
    for (int ch = 0; ch < NCHUNK; ch++) {
        int n = d_cnt4[ch * NROWS + row];
        const unsigned short* lst = lrow + ch * SEG;
        for (int idx = 0; idx < n; idx++) {
            size_t j = base + lst[idx];
            float dj = __ldg(&d_dinv[j]);
            float2 xj = __ldg(&pos2[j]);
            wx0 += dj * xj.x;
            wx1 += dj * xj.y;
        }
    }
    float v = di * (wx0 * __ldg(&W1[f]) + wx1 * __ldg(&W1[128 + f])) + __ldg(&b1[f]);
    out[(size_t)row * 128 + f] = fmaxf(v, 0.0f);
}

// ---------------- GCN2 aggregation: out = (dinv_i*(Σ Z2[j] + Z2[i]) + b2) * mask ----------------
__global__ void k_agg2(const float* __restrict__ Zin, const float* __restrict__ bias,
                       float* __restrict__ out) {
    int row = blockIdx.x;
    int f = threadIdx.x;
    int t = row / MM;
    size_t base = (size_t)t * MM;
    float acc = Zin[(size_t)row * 128 + f];
    const unsigned short* lrow = &d_nbr[(size_t)row * CAP];
    #pragma unroll
    for (int ch = 0; ch < NCHUNK; ch++) {
        int n = d_cnt4[ch * NROWS + row];
        const unsigned short* lst = lrow + ch * SEG;
        for (int idx = 0; idx < n; idx++) {
            int j = lst[idx];
            acc += Zin[(base + j) * 128 + f];
        }
    }
    float v = d_dinv[row] * acc + __ldg(&bias[f]);
    out[(size_t)row * 128 + f] = v * d_maskf[row];
}

// ---------------- tiled GEMM, K=128 fixed, packed f32x2 ----------------
// mode 0 (Z2):    A row = r,                B = W2   [k][c],  epi: *dinv[r]
// mode 1 (gates): A row = (r%20)*2000+r/20, B = W_ih [c][k],  epi: + b_ih[c]+b_hh[c]
__global__ void __launch_bounds__(256)
k_gemm(const float* __restrict__ A, const float* __restrict__ B, float* __restrict__ C,
       const float* __restrict__ bia, const float* __restrict__ bib,
       int mode, int ncols) {
    extern __shared__ float sm[];
    float* As = sm;            // [64][128]
    float* Bs = sm + 64 * 128; // [128][130]
    int r0 = blockIdx.x * 64, c0 = blockIdx.y * 128;
    int tid = threadIdx.x;

    for (int i = tid; i < 64 * 32; i += 256) {
        int row = i / 32, k4 = i % 32;
        int gr = r0 + row;
        int arow = (mode == 1) ? ((gr % TT) * MM + gr / TT) : gr;
        ((float4*)As)[row * 32 + k4] = ((const float4*)A)[(size_t)arow * 32 + k4];
    }
    if (mode == 1) {
        for (int i = tid; i < 128 * 32; i += 256) {
            int c = i / 32, k4 = i % 32;
            float4 v = ((const float4*)B)[(size_t)(c0 + c) * 32 + k4];
            Bs[c * 130 + 4 * k4 + 0] = v.x; Bs[c * 130 + 4 * k4 + 1] = v.y;
            Bs[c * 130 + 4 * k4 + 2] = v.z; Bs[c * 130 + 4 * k4 + 3] = v.w;
        }
    } else {
        for (int i = tid; i < 128 * 32; i += 256) {
            int k = i / 32, c4 = i % 32;
            float4 v = ((const float4*)B)[(size_t)k * 32 + c4];
            Bs[(4 * c4 + 0) * 130 + k] = v.x; Bs[(4 * c4 + 1) * 130 + k] = v.y;
            Bs[(4 * c4 + 2) * 130 + k] = v.z; Bs[(4 * c4 + 3) * 130 + k] = v.w;
        }
    }
    __syncthreads();

    int tx = tid % 32, ty = tid / 32;
    unsigned long long acc[8][4];
    #pragma unroll
    for (int rr = 0; rr < 8; rr++)
        #pragma unroll
        for (int cc = 0; cc < 4; cc++) acc[rr][cc] = 0ull;

    const ulonglong2* As2 = (const ulonglong2*)As;
    #pragma unroll 4
    for (int k4 = 0; k4 < 32; k4++) {
        ulonglong2 a[8];
        #pragma unroll
        for (int rr = 0; rr < 8; rr++) a[rr] = As2[(ty * 8 + rr) * 32 + k4];
        #pragma unroll
        for (int cc = 0; cc < 4; cc++) {
            int c = tx + 32 * cc;
            const unsigned long long* bp = (const unsigned long long*)(Bs + c * 130 + 4 * k4);
            unsigned long long b0 = bp[0], b1 = bp[1];
            #pragma unroll
            for (int rr = 0; rr < 8; rr++) {
                FMA2(acc[rr][cc], a[rr].x, b0);
                FMA2(acc[rr][cc], a[rr].y, b1);
            }
        }
    }
    #pragma unroll
    for (int cc = 0; cc < 4; cc++) {
        int c = tx + 32 * cc;
        float bv = (mode == 1) ? (__ldg(&bia[c0 + c]) + __ldg(&bib[c0 + c])) : 0.0f;
        #pragma unroll
        for (int rr = 0; rr < 8; rr++) {
            int r = r0 + ty * 8 + rr;
            float lo, hi; UNPK(lo, hi, acc[rr][cc]);
            float v = lo + hi;
            if (mode == 1) v += bv;
            else           v *= d_dinv[r];
            C[(size_t)r * ncols + c0 + c] = v;
        }
    }
}

// ---------------- persistent LSTM: 20 blocks, 512 threads, bf16 weight tail ----------------
// Thread g -> gate row grow=q*128+j. Weights k[0:96) in 48 ull fp32 registers;
// k[96:128) as packed bf16x2 in smem (64B/thread -> 256 wf/step vs 512 fp32),
// expanded to f32 pairs in-flight (bf16 = top 16 bits of f32).
// Shuffle gate exchange, double-buffered h, one barrier/step.
__global__ void __launch_bounds__(512, 1)
k_lstm(const float* __restrict__ Whh) {
    extern __shared__ float smf[];
    unsigned* Wt = (unsigned*)smf;          // [16][512] u32: bf16x2, k=96+2i,96+2i+1
    float* hsm = smf + 16 * 512;            // [2][128] double-buffered h
    int t = blockIdx.x, g = threadIdx.x;
    int q = g & 3, j = g >> 2;
    int grow = q * 128 + j;                 // gate row in [512]

    unsigned long long w[48];
    const unsigned long long* wrow = (const unsigned long long*)(Whh + (size_t)grow * 128);
    #pragma unroll
    for (int i = 0; i < 48; i++) w[i] = wrow[i];
    #pragma unroll
    for (int i = 0; i < 16; i++) {          // tail k = 96+2i, 96+2i+1 -> bf16x2
        float2 wp = *(const float2*)(Whh + (size_t)grow * 128 + 96 + 2 * i);
        __nv_bfloat162 b2 = __float22bfloat162_rn(wp);
        Wt[i * 512 + g] = *(unsigned*)&b2;  // low 16 = k even, high 16 = k odd
    }

    float c = 0.0f;
    if (g < 128) hsm[g] = 0.0f;             // buffer 0
    __syncthreads();

    float nextg = d_gpre[(size_t)t * 512 + grow];   // m = 0
    for (int m = 0; m < MM; m++) {
        float gp = nextg;
        if (m < MM - 1) nextg = d_gpre[(size_t)((m + 1) * TT + t) * 512 + grow];
        const ulonglong2* h2 = (const ulonglong2*)(hsm + (m & 1) * 128);
        unsigned long long accA = 0ull, accB = 0ull;
        #pragma unroll
        for (int jj = 0; jj < 24; jj++) {   // k = 0..95, fp32 register weights
            ulonglong2 hv = h2[jj];
            FMA2(accA, hv.x, w[2 * jj]);
            FMA2(accB, hv.y, w[2 * jj + 1]);
        }
        #pragma unroll
        for (int kq = 0; kq < 8; kq++) {    // k = 96..127, bf16 smem weights
            ulonglong2 hv = h2[24 + kq];
            unsigned w0 = Wt[(2 * kq) * 512 + g];
            unsigned w1 = Wt[(2 * kq + 1) * 512 + g];
            unsigned long long wa = ((unsigned long long)(w0 & 0xFFFF0000u) << 32)
                                  | (unsigned long long)(w0 << 16);
            unsigned long long wb = ((unsigned long long)(w1 & 0xFFFF0000u) << 32)
                                  | (unsigned long long)(w1 << 16);
            FMA2(accA, hv.x, wa);
            FMA2(accB, hv.y, wb);
        }
        float loA, hiA, loB, hiB;
        UNPK(loA, hiA, accA); UNPK(loB, hiB, accB);
        float part = (loA + hiA) + (loB + hiB) + gp;
        // branchless nonlinearity: tanh(x) = 2*sigm(2x)-1
        float xin = (q == 2) ? 2.0f * part : part;
        float s = sigm_f(xin);
        float act = (q == 2) ? fmaf(2.0f, s, -1.0f) : s;
        // gate exchange within warp: lanes q=0 gather f,g,o from lanes +1,+2,+3
        float a1 = __shfl_down_sync(0xffffffffu, act, 1);
        float a2 = __shfl_down_sync(0xffffffffu, act, 2);
        float a3 = __shfl_down_sync(0xffffffffu, act, 3);
        if (q == 0) {
            c = a1 * c + act * a2;                // f*c + i*g
            float hn = a3 * tanh_f(c);            // o*tanh(c)
            hsm[((m & 1) ^ 1) * 128 + j] = hn;    // write buffer
            d_lstm[(size_t)(m * TT + t) * 128 + j] = hn;
        }
        __syncthreads();
    }
}

// ---------------- fused FC1(relu)+FC2, 64 rows/block, packed f32x2 ----------------
__global__ void __launch_bounds__(256)
k_fc(const float* __restrict__ fc1w, const float* __restrict__ fc1b,
     const float* __restrict__ fc2w, const float* __restrict__ fc2b,
     float* __restrict__ out) {
    extern __shared__ float sm[];
    float* w1t = sm;                   // [64][130]
    float* w2t = w1t + 64 * 130;       // [32][66]
    float* xs  = w2t + 32 * 66;        // [64][128]
    float* mid = xs  + 64 * 128;       // [64][66]
    int tid = threadIdx.x;

    for (int i = tid; i < 128 * 64; i += 256) {
        int k = i >> 6, cc = i & 63;
        w1t[cc * 130 + k] = fc1w[i];
    }
    for (int i = tid; i < 64 * 32; i += 256) {
        int k = i >> 5, o = i & 31;
        w2t[o * 66 + k] = fc2w[i];
    }
    int rbase = blockIdx.x * 64;
    for (int i = tid; i < 64 * 32; i += 256)
        ((float4*)xs)[i] = ((const float4*)d_lstm)[(size_t)rbase * 32 + i];
    __syncthreads();

    int r = tid >> 2, q = tid & 3;
    {
        unsigned long long acc[16];
        #pragma unroll
        for (int j = 0; j < 16; j++) acc[j] = 0ull;
        const unsigned long long* xr = (const unsigned long long*)(xs + r * 128);
        #pragma unroll 4
        for (int kp = 0; kp < 64; kp++) {
            unsigned long long xv = xr[kp];
            #pragma unroll
            for (int j = 0; j < 16; j++)
                FMA2(acc[j], xv, *(const unsigned long long*)(w1t + (q * 16 + j) * 130 + 2 * kp));
        }
        #pragma unroll
        for (int j = 0; j < 16; j++) {
            float lo, hi; UNPK(lo, hi, acc[j]);
            int cc = q * 16 + j;
            mid[r * 66 + cc] = fmaxf(lo + hi + __ldg(&fc1b[cc]), 0.0f);
        }
    }
    __syncthreads();
    {
        unsigned long long acc[8];
        #pragma unroll
        for (int j = 0; j < 8; j++) acc[j] = 0ull;
        const unsigned long long* mr = (const unsigned long long*)(mid + r * 66);
        #pragma unroll 4
        for (int kp = 0; kp < 32; kp++) {
            unsigned long long mv = mr[kp];
            #pragma unroll
            for (int j = 0; j < 8; j++)
                FMA2(acc[j], mv, *(const unsigned long long*)(w2t + (q * 8 + j) * 66 + 2 * kp));
        }
        #pragma unroll
        for (int j = 0; j < 8; j++) {
            float lo, hi; UNPK(lo, hi, acc[j]);
            int o = q * 8 + j;
            out[(size_t)(rbase + r) * 32 + o] = lo + hi + __ldg(&fc2b[o]);
        }
    }
}

// ---------------- launch ----------------
extern "C" void kernel_launch(void* const* d_in, const int* in_sizes, int n_in,
                              void* d_out, int out_size) {
    const float* positions = (const float*)d_in[0];
    const float* adjacency = (const float*)d_in[1];
    const unsigned int* ego = (const unsigned int*)d_in[2];
    const float* W1   = (const float*)d_in[3];
    const float* b1   = (const float*)d_in[4];
    const float* W2   = (const float*)d_in[5];
    const float* b2   = (const float*)d_in[6];
    const float* W_ih = (const float*)d_in[7];
    const float* W_hh = (const float*)d_in[8];
    const float* b_ih = (const float*)d_in[9];
    const float* b_hh = (const float*)d_in[10];
    const float* fc1w = (const float*)d_in[11];
    const float* fc1b = (const float*)d_in[12];
    const float* fc2w = (const float*)d_in[13];
    const float* fc2b = (const float*)d_in[14];
    float* out = (float*)d_out;

    static const int GEMM_SMEM = (64 * 128 + 128 * 130) * 4;            // 99328
    static const int LSTM_SMEM = (16 * 512 + 256) * 4;                  // 33792
    static const int FC_SMEM   = (64 * 130 + 32 * 66 + 64 * 128 + 64 * 66) * 4;  // 91392
    cudaFuncSetAttribute(k_gemm, cudaFuncAttributeMaxDynamicSharedMemorySize, GEMM_SMEM);
    cudaFuncSetAttribute(k_lstm, cudaFuncAttributeMaxDynamicSharedMemorySize, LSTM_SMEM);
    cudaFuncSetAttribute(k_fc,   cudaFuncAttributeMaxDynamicSharedMemorySize, FC_SMEM);

    float* bufA; cudaGetSymbolAddress((void**)&bufA, d_bufA);
    float* bufB; cudaGetSymbolAddress((void**)&bufB, d_bufB);
    float* gpre; cudaGetSymbolAddress((void**)&gpre, d_gpre);

    // launch index:                                                                  idx
    k_extract<<<dim3(8, TT, NCHUNK), 256>>>(adjacency, ego);                       // 0
    k_agg1<<<NROWS, 128>>>((const float2*)positions, W1, b1, bufB);                // 1
    k_gemm<<<dim3(625, 1), 256, GEMM_SMEM>>>(bufB, W2, bufA, 0, 0, 0, 128);        // 2
    k_agg2<<<NROWS, 128>>>(bufA, b2, bufB);                                        // 3
    k_gemm<<<dim3(625, 4), 256, GEMM_SMEM>>>(bufB, W_ih, gpre, b_ih, b_hh, 1, 512);// 4
    k_lstm<<<TT, 512, LSTM_SMEM>>>(W_hh);                                          // 5 <- ncu -s 5
    k_fc<<<625, 256, FC_SMEM>>>(fc1w, fc1b, fc2w, fc2b, out);                      // 6
}